// round 8
// baseline (speedup 1.0000x reference)
#include <cuda_runtime.h>
#include <math.h>

#define BB 8
#define CC 4
#define HH 192
#define WW 192
#define HW (HH*WW)
#define NP 24          // (batch, class) pairs: 8 * 3
#define NM 48          // masks: pair*2 + {0:pred surface, 1:gt surface}
#define SENT_KEY 73727 // sentinel key for f >= 1e9 (empty source surface)
#define RPB 8          // rows per rowpass block

__device__ unsigned char  d_pred[BB*HW];
__device__ unsigned char  d_surf[NM*HW];
__device__ unsigned char  d_cols[NM*HW];     // per-row compacted sample columns
__device__ short          d_cnt[NM*HH];      // samples per row
__device__ unsigned short d_g16[NM*HW];      // column-pass squared distance (65535 = inf)
__device__ int            d_keys[NM*HW];     // appended squared-distance keys per mask
__device__ int            d_kcnt[NM];        // append counters
__device__ float          d_res[NM*2];       // [m][0]=p95, [m][1]=p100
__device__ int            d_done;            // select completion ticket

// ---------------------------------------------------------------- argmax (softmax monotone; first-max tie rule)
// Also clears the per-mask key counters and the completion ticket.
__global__ void argmax_kernel(const float* __restrict__ logits) {
    int idx = blockIdx.x*blockDim.x + threadIdx.x;
    if (idx < NM) d_kcnt[idx] = 0;
    if (idx == NM) d_done = 0;
    int pix4 = idx * 4;
    if (pix4 >= BB*HW) return;
    int b = pix4 / HW;
    int p = pix4 - b*HW;
    const float* base = logits + (size_t)b*CC*HW + p;
    float4 v0 = *(const float4*)(base);
    float4 v1 = *(const float4*)(base + HW);
    float4 v2 = *(const float4*)(base + 2*HW);
    float4 v3 = *(const float4*)(base + 3*HW);
    uchar4 r;
    #define AMAX(comp, dst) { \
        float bv = v0.comp; int bi = 0; \
        if (v1.comp > bv) { bv = v1.comp; bi = 1; } \
        if (v2.comp > bv) { bv = v2.comp; bi = 2; } \
        if (v3.comp > bv) { bv = v3.comp; bi = 3; } \
        dst = (unsigned char)bi; }
    AMAX(x, r.x) AMAX(y, r.y) AMAX(z, r.z) AMAX(w, r.w)
    #undef AMAX
    *(uchar4*)(d_pred + pix4) = r;
}

// ---------------------------------------------------------------- fused surface + row compaction
// One warp per (pair,row). Computes pred & gt 4-neighbor surfaces (border = background),
// writes d_surf (for colpass) and ballot-compacts surface columns into d_cols/d_cnt.
// target is int32 (JAX x64-disabled downcasts the reference's int64).
__global__ void surfcompact_kernel(const int* __restrict__ target) {
    int wid  = threadIdx.x >> 5;
    int lane = threadIdx.x & 31;
    int gw = blockIdx.x*4 + wid;                 // row id in [0, NP*HH)
    if (gw >= NP*HH) return;
    int pair = gw / HH;
    int i    = gw - pair*HH;
    int b = pair / 3;
    int c = pair - b*3 + 1;
    const unsigned char* P = d_pred + b*HW;
    const int* T = target + (size_t)b*HW;
    int mp = pair*2, mg = pair*2 + 1;
    unsigned char* outp = d_cols + mp*HW + i*WW;
    unsigned char* outg = d_cols + mg*HW + i*WW;
    int basep = 0, baseg = 0;
    #pragma unroll
    for (int ch = 0; ch < 6; ch++) {
        int j = ch*32 + lane;
        int pix = i*WW + j;
        // pred surface
        {
            bool fg = (P[pix] == c);
            bool s = false;
            if (fg) {
                bool up = (i > 0)    && (P[pix-WW] == c);
                bool dn = (i < HH-1) && (P[pix+WW] == c);
                bool lf = (j > 0)    && (P[pix-1]  == c);
                bool rt = (j < WW-1) && (P[pix+1]  == c);
                s = !(up && dn && lf && rt);
            }
            d_surf[mp*HW + pix] = s ? 1 : 0;
            unsigned msk = __ballot_sync(0xffffffffu, s);
            if (s) outp[basep + __popc(msk & ((1u << lane) - 1u))] = (unsigned char)j;
            basep += __popc(msk);
        }
        // gt surface
        {
            bool fg = (T[pix] == c);
            bool s = false;
            if (fg) {
                bool up = (i > 0)    && (T[pix-WW] == c);
                bool dn = (i < HH-1) && (T[pix+WW] == c);
                bool lf = (j > 0)    && (T[pix-1]  == c);
                bool rt = (j < WW-1) && (T[pix+1]  == c);
                s = !(up && dn && lf && rt);
            }
            d_surf[mg*HW + pix] = s ? 1 : 0;
            unsigned msk = __ballot_sync(0xffffffffu, s);
            if (s) outg[baseg + __popc(msk & ((1u << lane) - 1u))] = (unsigned char)j;
            baseg += __popc(msk);
        }
    }
    if (lane == 0) {
        d_cnt[mp*HH + i] = (short)basep;
        d_cnt[mg*HH + i] = (short)baseg;
    }
}

// ---------------------------------------------------------------- pass 1: per-column squared distance to nearest surface row
// grid (48 masks, 3 col-groups of 64). Forward: downward count into smem (0 <=> surface voxel).
// Backward: pure smem/register, write d^2 as u16 (65535 = empty column).
__global__ void colpass_kernel() {
    int m = blockIdx.x;
    int j = blockIdx.y*64 + threadIdx.x;
    int t = threadIdx.x;
    __shared__ unsigned char dtmp[HH*64];
    const unsigned char* s = d_surf + m*HW;
    unsigned short* g = d_g16 + m*HW;
    int cnt = 255;
    #pragma unroll 16
    for (int i = 0; i < HH; i++) {
        unsigned char sv = s[i*WW + j];
        cnt = sv ? 0 : min(cnt + 1, 255);
        dtmp[i*64 + t] = (unsigned char)cnt;
    }
    cnt = 255;
    #pragma unroll 16
    for (int i = HH-1; i >= 0; i--) {
        int du = (int)dtmp[i*64 + t];
        cnt = (du == 0) ? 0 : min(cnt + 1, 255);
        int d = min(cnt, du);
        g[i*WW + j] = (d >= HH) ? (unsigned short)65535 : (unsigned short)(d*d);
    }
}

// ---------------------------------------------------------------- pass 2: min-plus at sampled voxels via exact outward pruning
// f = min_jp (jj-jp)^2 + g[jp]. Scan d outward from jj; stop when d^2 >= v (g >= 0 so no
// farther jp can improve — exact; the unrolled extra candidate is a genuine jp term).
// All values exact f32 integers (< 2^24) or ~1e9. 8 rows per block; samples flattened.
__global__ void __launch_bounds__(256) rowpass_kernel() {
    int m  = blockIdx.x;
    int i0 = blockIdx.y * RPB;
    __shared__ float gs[RPB][WW];
    __shared__ short offs[RPB + 1];
    if (threadIdx.x == 0) {
        int acc = 0;
        #pragma unroll
        for (int r = 0; r < RPB; r++) {
            offs[r] = (short)acc;
            acc += (int)d_cnt[(m ^ 1)*HH + i0 + r];
        }
        offs[RPB] = (short)acc;
    }
    __syncthreads();
    int total = (int)offs[RPB];
    if (total == 0) return;
    const unsigned short* gsrc = d_g16 + m*HW + i0*WW;
    for (int k = threadIdx.x; k < RPB*WW; k += blockDim.x) {
        unsigned short v = gsrc[k];
        ((float*)gs)[k] = (v == 65535) ? 1e9f : (float)v;
    }
    __syncthreads();
    int lane = threadIdx.x & 31;
    const unsigned char* colbase = d_cols + (m ^ 1)*HW + i0*WW;
    for (int t0 = 0; t0 < total; t0 += blockDim.x) {
        int t = t0 + threadIdx.x;
        bool act = (t < total);
        int key = 0;
        if (act) {
            int r = 0;
            #pragma unroll
            for (int rr = 1; rr < RPB; rr++) r += (t >= (int)offs[rr]);
            int idx = t - (int)offs[r];
            int jj = (int)colbase[r*WW + idx];
            const float* grow = gs[r];
            float v = grow[jj];
            for (int dd = 1; dd < WW; dd += 2) {
                float d2a = (float)(dd*dd);
                if (d2a >= v) break;
                float d2b = (float)((dd+1)*(dd+1));
                int jl = jj - dd, jr = jj + dd;
                float ca = (jl >= 0) ? d2a + grow[jl] : 3.0e9f;
                float cb = (jr < WW) ? d2a + grow[jr] : 3.0e9f;
                float cc2 = (jl - 1 >= 0) ? d2b + grow[jl-1] : 3.0e9f;
                float cd = (jr + 1 < WW) ? d2b + grow[jr+1] : 3.0e9f;
                v = fminf(fminf(v, fminf(ca, cb)), fminf(cc2, cd));
            }
            key = (v > 73000.0f) ? SENT_KEY : (int)v;
        }
        unsigned msk = __ballot_sync(0xffffffffu, act);
        if (act) {
            int rank = __popc(msk & ((1u << lane) - 1u));
            int base = 0;
            if (rank == 0) base = atomicAdd(&d_kcnt[m], __popc(msk));
            base = __shfl_sync(msk, base, __ffs(msk) - 1);
            d_keys[m*HW + base + rank] = key;
        }
    }
}

// ---------------------------------------------------------------- per-mask selection + fused final reduce
// p100 = max key (rank n). p95 = rank ceil(0.95f*n) via smem coarse(288) + fine(256) hists.
// Last block to finish (threadfence + atomic ticket) combines all 48 results.
__global__ void select_kernel(float* __restrict__ out) {
    int m = blockIdx.x;
    int t = threadIdx.x;       // 256 threads
    int n = d_kcnt[m];
    if (n == 0) {
        if (t < 2) d_res[m*2 + t] = INFINITY;
    } else {
        __shared__ int hist[288];
        __shared__ int red[256];
        __shared__ int fine[256];
        __shared__ int cbS, rremS;
        for (int k = t; k < 288; k += 256) hist[k] = 0;
        fine[t] = 0;
        __syncthreads();
        const int* keys = d_keys + m*HW;
        int mx = 0;
        for (int k = t; k < n; k += 256) {
            int key = keys[k];
            mx = max(mx, key);
            atomicAdd(&hist[key >> 8], 1);
        }
        red[t] = mx;
        __syncthreads();
        #pragma unroll
        for (int s = 128; s > 0; s >>= 1) {
            if (t < s) red[t] = max(red[t], red[t + s]);
            __syncthreads();
        }
        if (t == 0) {
            int r95 = (int)ceilf(0.95f * (float)n);   // matches jnp f32 semantics
            if (r95 < 1) r95 = 1;
            if (r95 > n) r95 = n;
            int cum = 0, cb = 287;
            for (int k = 0; k < 288; k++) {
                if (cum + hist[k] >= r95) { cb = k; break; }
                cum += hist[k];
            }
            cbS = cb; rremS = r95 - cum;
        }
        __syncthreads();
        int cb = cbS;
        for (int k = t; k < n; k += 256) {
            int key = keys[k];
            if ((key >> 8) == cb) atomicAdd(&fine[key & 255], 1);
        }
        __syncthreads();
        if (t == 0) {
            int cum = 0, key95 = cb << 8;
            for (int k = 0; k < 256; k++) {
                cum += fine[k];
                if (cum >= rremS) { key95 += k; break; }
            }
            int keymax = red[0];
            d_res[m*2 + 0] = (key95  == SENT_KEY) ? sqrtf(1e9f) : sqrtf((float)key95);
            d_res[m*2 + 1] = (keymax == SENT_KEY) ? sqrtf(1e9f) : sqrtf((float)keymax);
        }
    }
    // fused final: last block to finish combines (order-independent -> deterministic)
    __threadfence();
    __syncthreads();
    if (t == 0) {
        if (atomicAdd(&d_done, 1) == NM - 1) {
            float s100 = 0.0f, s95 = 0.0f;
            #pragma unroll
            for (int p = 0; p < NP; p++) {
                s95  += fmaxf(d_res[(2*p)*2 + 0], d_res[(2*p+1)*2 + 0]);
                s100 += fmaxf(d_res[(2*p)*2 + 1], d_res[(2*p+1)*2 + 1]);
            }
            out[0] = s100 / (float)NP;
            out[1] = s95  / (float)NP;
        }
    }
}

extern "C" void kernel_launch(void* const* d_in, const int* in_sizes, int n_in,
                              void* d_out, int out_size) {
    const float* logits = (const float*)d_in[0];
    const int*   target = (const int*)d_in[1];
    float* out = (float*)d_out;

    argmax_kernel     <<<(BB*HW/4 + 255)/256, 256>>>(logits);
    surfcompact_kernel<<<(NP*HH + 3)/4, 128>>>(target);
    colpass_kernel    <<<dim3(NM, 3), 64>>>();
    rowpass_kernel    <<<dim3(NM, HH/RPB), 256>>>();
    select_kernel     <<<NM, 256>>>(out);
}

// round 9
// speedup vs baseline: 1.3265x; 1.3265x over previous
#include <cuda_runtime.h>
#include <math.h>

#define BB 8
#define CC 4
#define HH 192
#define WW 192
#define HW (HH*WW)
#define NP 24          // (batch, class) pairs
#define NM 48          // (pair, direction)
#define SENT_KEY 73727 // key for f >= 1e9 (empty source surface)
#define LIST_MAX 20480

// dynamic smem layout (bytes)
#define OFF_G     0            // u16 [HW]        73728
#define OFF_LIST  73728        // u16 [LIST_MAX]  40960
#define OFF_KEYS  114688       // int [LIST_MAX]  81920
#define OFF_FGP   196608       // u32 [1152]
#define OFF_FGG   201216       // u32 [1152]
#define OFF_SFP   205824       // u32 [1152]
#define OFF_SFG   210432       // u32 [1152]
#define OFF_HIST  215040       // int [288]
#define OFF_FINE  216192       // int [256]
#define OFF_ROWC  217216       // int [192]
#define OFF_ROWO  217984       // int [192]
#define OFF_MISC  218752       // int [8]
#define SMEM_TOTAL 218784

__device__ float d_res[NM*2];  // [m][0]=p95, [m][1]=p100
__device__ int   d_done = 0;   // ticket; last block resets to 0 for next replay

extern __shared__ char smem[];

__global__ void __launch_bounds__(1024) mega_kernel(const float* __restrict__ logits,
                                                    const int* __restrict__ target,
                                                    float* __restrict__ out) {
    unsigned short* gS   = (unsigned short*)(smem + OFF_G);
    unsigned short* list = (unsigned short*)(smem + OFF_LIST);
    int*      keys = (int*)(smem + OFF_KEYS);
    unsigned* fgP  = (unsigned*)(smem + OFF_FGP);   // fgP,fgG contiguous
    unsigned* fgG  = (unsigned*)(smem + OFF_FGG);
    unsigned* sfP  = (unsigned*)(smem + OFF_SFP);
    unsigned* sfG  = (unsigned*)(smem + OFF_SFG);
    int* hist = (int*)(smem + OFF_HIST);            // hist,fine contiguous (544 ints)
    int* rowc = (int*)(smem + OFF_ROWC);
    int* rowo = (int*)(smem + OFF_ROWO);
    int* misc = (int*)(smem + OFF_MISC);

    const int T = 1024;
    int m = blockIdx.x;
    int pairI = m >> 1;
    int b = pairI / 3;
    int c = pairI - b*3 + 1;
    int tid = threadIdx.x;
    int lane = tid & 31;
    int wid = tid >> 5;

    for (int k = tid; k < 2304; k += T) fgP[k] = 0;
    if (tid == 0) misc[1] = 0;   // running max key
    __syncthreads();

    // ---- A: fg bitmaps (pred via argmax of logits — softmax monotone, first-max ties; target is int32)
    const float* lg = logits + (size_t)b*CC*HW;
    for (int q = tid; q < HW/4; q += T) {
        int p4 = q*4;
        float4 v0 = *(const float4*)(lg + p4);
        float4 v1 = *(const float4*)(lg + HW + p4);
        float4 v2 = *(const float4*)(lg + 2*HW + p4);
        float4 v3 = *(const float4*)(lg + 3*HW + p4);
        unsigned bits = 0;
        #define AM(cp, bit) { float bv = v0.cp; int bi = 0; \
            if (v1.cp > bv) { bv = v1.cp; bi = 1; } \
            if (v2.cp > bv) { bv = v2.cp; bi = 2; } \
            if (v3.cp > bv) { bv = v3.cp; bi = 3; } \
            if (bi == c) bits |= bit; }
        AM(x,1u) AM(y,2u) AM(z,4u) AM(w,8u)
        #undef AM
        if (bits) atomicOr(&fgP[p4 >> 5], bits << (p4 & 31));
    }
    const int* tg = target + (size_t)b*HW;
    for (int q = tid; q < HW/4; q += T) {
        int p4 = q*4;
        int4 tv = *(const int4*)(tg + p4);
        unsigned bits = (tv.x==c?1u:0u)|(tv.y==c?2u:0u)|(tv.z==c?4u:0u)|(tv.w==c?8u:0u);
        if (bits) atomicOr(&fgG[p4 >> 5], bits << (p4 & 31));
    }
    __syncthreads();

    // ---- B: 4-neighbor surfaces via bit ops (image border = background)
    for (int idx = tid; idx < 2304; idx += T) {
        const unsigned* fg = (idx < 1152) ? fgP : fgG;
        unsigned* sf = (idx < 1152) ? sfP : sfG;
        int k = (idx < 1152) ? idx : idx - 1152;
        int i = k / 6, w = k - (k/6)*6;
        unsigned f  = fg[k];
        unsigned up = (i > 0)    ? fg[k-6] : 0u;
        unsigned dn = (i < HH-1) ? fg[k+6] : 0u;
        unsigned lw = (w > 0) ? fg[k-1] : 0u;
        unsigned nx = (w < 5) ? fg[k+1] : 0u;
        unsigned lf = (f << 1) | (lw >> 31);
        unsigned rt = (f >> 1) | (nx << 31);
        sf[k] = f & ~(up & dn & lf & rt);
    }
    __syncthreads();

    const unsigned* sS = (m & 1) ? sfG : sfP;   // source surface (this mask's distance field)
    const unsigned* sO = (m & 1) ? sfP : sfG;   // opposite surface (sample points)

    // ---- C (warps 0-5): per-column EDT into smem g (exact; 65535 = empty column)
    // ---- D1 (warps 6-11, concurrent): per-row popcounts of the sample surface
    if (tid < WW) {
        int j = tid; int ws = j >> 5; unsigned bm = 1u << (j & 31);
        int cnt = 255;
        for (int i = 0; i < HH; i++) {
            bool sv = (sS[i*6 + ws] & bm) != 0;
            cnt = sv ? 0 : min(cnt + 1, 255);
            gS[i*WW + j] = (unsigned short)cnt;
        }
        cnt = 255;
        for (int i = HH-1; i >= 0; i--) {
            int du = gS[i*WW + j];
            cnt = (du == 0) ? 0 : min(cnt + 1, 255);
            int d = min(cnt, du);
            gS[i*WW + j] = (d >= HH) ? (unsigned short)65535 : (unsigned short)(d*d);
        }
    } else if (tid < 2*WW) {
        int r = tid - WW;
        int s = 0;
        #pragma unroll
        for (int w = 0; w < 6; w++) s += __popc(sO[r*6 + w]);
        rowc[r] = s;
    }
    __syncthreads();

    // ---- D2: exclusive prefix over 192 row counts (warp 0)
    if (tid < 32) {
        int loc[6]; int lsum = 0;
        #pragma unroll
        for (int k = 0; k < 6; k++) { loc[k] = lsum; lsum += rowc[tid*6 + k]; }
        int x = lsum;
        #pragma unroll
        for (int off = 1; off < 32; off <<= 1) {
            int y = __shfl_up_sync(0xffffffffu, x, off);
            if (lane >= off) x += y;
        }
        int excl = x - lsum;
        #pragma unroll
        for (int k = 0; k < 6; k++) rowo[tid*6 + k] = excl + loc[k];
        if (tid == 31) misc[0] = x;   // total sample count n
    }
    __syncthreads();
    int n = misc[0];

    // ---- D3: scatter (row,col) sample list at known offsets (no atomics)
    for (int r = wid; r < HH; r += 32) {
        int base = rowo[r];
        #pragma unroll
        for (int w = 0; w < 6; w++) {
            unsigned bits = sO[r*6 + w];
            if ((bits >> lane) & 1)
                list[base + __popc(bits & ((1u << lane) - 1u))] =
                    (unsigned short)((r << 8) | (w*32 + lane));
            base += __popc(bits);
        }
    }
    for (int k = tid; k < 544; k += T) hist[k] = 0;   // hist + fine
    __syncthreads();

    if (n > 0) {
        // ---- E: exact outward-pruned min-plus per sample; warp-aggregated histogram
        int locmax = 0;
        for (int s0 = 0; s0 < n; s0 += T) {
            int s = s0 + tid;
            bool act = (s < n);
            int key = 0;
            if (act) {
                int e = (int)list[s];
                int r = e >> 8, jj = e & 255;
                const unsigned short* grow = gS + r*WW;
                unsigned short raw = grow[jj];
                float v = (raw == 65535) ? 1e9f : (float)raw;
                for (int dd = 1; dd < WW; dd += 2) {
                    float d2a = (float)(dd*dd);
                    if (d2a >= v) break;                     // exact: g >= 0
                    float d2b = (float)((dd+1)*(dd+1));
                    int jl = jj - dd, jr = jj + dd;
                    float ca = 3e9f, cb2 = 3e9f, cc = 3e9f, cd = 3e9f;
                    unsigned short u;
                    if (jl >= 0)   { u = grow[jl];   ca  = d2a + ((u==65535)?1e9f:(float)u); }
                    if (jr < WW)   { u = grow[jr];   cb2 = d2a + ((u==65535)?1e9f:(float)u); }
                    if (jl-1 >= 0) { u = grow[jl-1]; cc  = d2b + ((u==65535)?1e9f:(float)u); }
                    if (jr+1 < WW) { u = grow[jr+1]; cd  = d2b + ((u==65535)?1e9f:(float)u); }
                    v = fminf(fminf(v, fminf(ca, cb2)), fminf(cc, cd));
                }
                key = (v > 73000.0f) ? SENT_KEY : (int)v;    // exact integer or ~1e9
                keys[s] = key;
                locmax = max(locmax, key);
            }
            unsigned am = __ballot_sync(0xffffffffu, act);
            if (act) {
                int bin = key >> 8;
                unsigned grp = __match_any_sync(am, bin);
                if ((__ffs(grp) - 1) == lane) atomicAdd(&hist[bin], __popc(grp));
            }
        }
        atomicMax(&misc[1], locmax);
        __syncthreads();

        // ---- F: select p95 = rank ceil(0.95f*n); p100 = max
        if (tid == 0) {
            int r95 = (int)ceilf(0.95f * (float)n);          // matches jnp f32 semantics
            r95 = max(1, min(r95, n));
            int cum = 0, cb = 287;
            for (int k = 0; k < 288; k++) {
                if (cum + hist[k] >= r95) { cb = k; break; }
                cum += hist[k];
            }
            misc[2] = cb; misc[3] = r95 - cum;
        }
        __syncthreads();
        int cbv = misc[2];
        int* fine = (int*)(smem + OFF_FINE);
        for (int s0 = 0; s0 < n; s0 += T) {
            int s = s0 + tid;
            bool act = (s < n);
            int key = act ? keys[s] : -1;
            bool hit = act && ((key >> 8) == cbv);
            unsigned am = __ballot_sync(0xffffffffu, hit);
            if (hit) {
                int fb = key & 255;
                unsigned grp = __match_any_sync(am, fb);
                if ((__ffs(grp) - 1) == lane) atomicAdd(&fine[fb], __popc(grp));
            }
        }
        __syncthreads();
        if (tid == 0) {
            int cum = 0, key95 = cbv << 8;
            for (int k = 0; k < 256; k++) {
                cum += fine[k];
                if (cum >= misc[3]) { key95 += k; break; }
            }
            int keymax = misc[1];
            d_res[m*2+0] = (key95  == SENT_KEY) ? sqrtf(1e9f) : sqrtf((float)key95);
            d_res[m*2+1] = (keymax == SENT_KEY) ? sqrtf(1e9f) : sqrtf((float)keymax);
        }
    } else {
        if (tid == 0) { d_res[m*2] = INFINITY; d_res[m*2+1] = INFINITY; }
    }

    // ---- G: ticket-fused final reduce (order-independent -> deterministic)
    __threadfence();
    __syncthreads();
    if (tid == 0 && atomicAdd(&d_done, 1) == NM - 1) {
        __threadfence();
        float s100 = 0.0f, s95 = 0.0f;
        #pragma unroll
        for (int p = 0; p < NP; p++) {
            s95  += fmaxf(d_res[(2*p)*2 + 0], d_res[(2*p+1)*2 + 0]);
            s100 += fmaxf(d_res[(2*p)*2 + 1], d_res[(2*p+1)*2 + 1]);
        }
        out[0] = s100 / (float)NP;
        out[1] = s95  / (float)NP;
        d_done = 0;   // reset for next replay
    }
}

extern "C" void kernel_launch(void* const* d_in, const int* in_sizes, int n_in,
                              void* d_out, int out_size) {
    const float* logits = (const float*)d_in[0];
    const int*   target = (const int*)d_in[1];
    float* out = (float*)d_out;

    cudaFuncSetAttribute(mega_kernel, cudaFuncAttributeMaxDynamicSharedMemorySize, SMEM_TOTAL);
    mega_kernel<<<NM, 1024, SMEM_TOTAL>>>(logits, target, out);
}